// round 6
// baseline (speedup 1.0000x reference)
#include <cuda_runtime.h>
#include <cuda_bf16.h>
#include <math.h>

// Problem constants (fixed by setup_inputs)
#define B_N 4096
#define M_N 256
#define D_N 256

#define TAU_INV_LOG2E 7.213475204444817f   // log2(e)/0.2
#define LAM_INV_LOG2E 0.18033688011112043f // log2(e)/8
#define TOPO_C 0.5f
#define LEN_C 0.01f
#define SP_C 0.001f

typedef unsigned long long u64;

// ---------------- packed f32x2 helpers (sm_103a) ----------------
__device__ __forceinline__ u64 f2add(u64 a, u64 b) {
    u64 o; asm("add.rn.f32x2 %0, %1, %2;" : "=l"(o) : "l"(a), "l"(b)); return o;
}
__device__ __forceinline__ u64 f2mul(u64 a, u64 b) {
    u64 o; asm("mul.rn.f32x2 %0, %1, %2;" : "=l"(o) : "l"(a), "l"(b)); return o;
}
__device__ __forceinline__ u64 f2fma(u64 a, u64 b, u64 c) {
    u64 o; asm("fma.rn.f32x2 %0, %1, %2, %3;" : "=l"(o) : "l"(a), "l"(b), "l"(c)); return o;
}
__device__ __forceinline__ u64 f2dup(float x) {
    u64 o; asm("mov.b64 %0, {%1, %1};" : "=l"(o) : "f"(x)); return o;
}
__device__ __forceinline__ u64 f2pack(float x, float y) {
    u64 o; asm("mov.b64 %0, {%1, %2};" : "=l"(o) : "f"(x), "f"(y)); return o;
}
__device__ __forceinline__ float2 f2unpack(u64 v) {
    float2 o; asm("mov.b64 {%0, %1}, %2;" : "=f"(o.x), "=f"(o.y) : "l"(v)); return o;
}
__device__ __forceinline__ float frcp(float x) {
    float r; asm("rcp.approx.ftz.f32 %0, %1;" : "=f"(r) : "f"(x)); return r;
}

// ---------------- device scratch (no allocations allowed) ----------------
__device__ float g_Wtp[128 * 512];        // W transposed, k-pair-major: [k2][m][2], 256KB
__device__ float g_xsq[B_N];              // ||x_b||^2
__device__ float g_wsq[M_N];              // ||w_m||^2
__device__ float g_factor[M_N];           // 1 + TOPO*degree[m]
__device__ float g_ep_rowsum[M_N];
__device__ float g_wl_rowsum[M_N];
__device__ float g_part[B_N];             // per-row data_term partials

// ---------------- K1: x-norms + w-norms + W transpose ----------------
// blocks 0..511: xsq (8 rows each, warp per row)
// blocks 512..527: W blocks (16 rows each): wsq + Wtp[k2*512 + m*2 + e] = W[m][2k2+e]
__global__ void __launch_bounds__(256) k_pre1(const float* __restrict__ X,
                                              const float* __restrict__ W) {
    const int t = threadIdx.x;
    const int lane = t & 31, warp = t >> 5;
    __shared__ float Ws[16][260];

    if (blockIdx.x < 512) {
        int row = blockIdx.x * 8 + warp;
        const float4* r4 = (const float4*)(X + (size_t)row * D_N);
        float s = 0.0f;
#pragma unroll
        for (int k = 0; k < 2; k++) {
            float4 v = r4[lane + 32 * k];
            s = fmaf(v.x, v.x, s); s = fmaf(v.y, v.y, s);
            s = fmaf(v.z, v.z, s); s = fmaf(v.w, v.w, s);
        }
#pragma unroll
        for (int o = 16; o; o >>= 1) s += __shfl_xor_sync(0xffffffffu, s, o);
        if (lane == 0) g_xsq[row] = s;
        return;
    }

    const int m0 = (blockIdx.x - 512) * 16;
    // load 16 W rows coalesced
#pragma unroll
    for (int p = 0; p < 16; p++) {
        int q = t + p * 256;
        int r = q >> 8, k = q & 255;
        Ws[r][k] = W[(size_t)(m0 + r) * D_N + k];
    }
    __syncthreads();

    // wsq: warp w handles rows 2w, 2w+1
#pragma unroll
    for (int rr = 0; rr < 2; rr++) {
        int row = warp * 2 + rr;
        float s = 0.0f;
#pragma unroll
        for (int p = 0; p < 8; p++) {
            float v = Ws[row][lane + 32 * p];
            s = fmaf(v, v, s);
        }
#pragma unroll
        for (int o = 16; o; o >>= 1) s += __shfl_xor_sync(0xffffffffu, s, o);
        if (lane == 0) g_wsq[m0 + row] = s;
    }

    // Wtp write: coalesced 128B per warp
#pragma unroll
    for (int p = 0; p < 16; p++) {
        int k2 = p * 8 + warp;       // 0..127
        int me = lane;               // 0..31
        int mloc = me >> 1, e = me & 1;
        g_Wtp[k2 * 512 + (m0 + mloc) * 2 + e] = Ws[mloc][k2 * 2 + e];
    }
}

// ---------------- K2: edges (coalesced dot via Wtp) ----------------
__global__ void __launch_bounds__(256) k_pre2(const float* __restrict__ W,
                                              const float* __restrict__ E) {
    const int i = blockIdx.x;
    const int j = threadIdx.x;
    const int lane = j & 31, warp = j >> 5;

    __shared__ __align__(16) float wis[D_N];
    __shared__ float red_ep[8];
    __shared__ float red_wl[8];

    wis[j] = W[i * D_N + j];
    __syncthreads();

    float lij = 0.5f * (E[i * M_N + j] + E[j * M_N + i]);
    float ep = __fdividef(1.0f, 1.0f + __expf(-lij));
    if (j == i) ep = 0.0f;

    // dot(w_i, w_j) via Wtp (lanes coalesced) + wis pairs (broadcast)
    const float* wtpj = g_Wtp + j * 2;
    u64 acc = 0ull;
#pragma unroll 8
    for (int k2 = 0; k2 < 128; k2++) {
        u64 wj2 = *(const u64*)(wtpj + k2 * 512);
        u64 xw  = *(const u64*)(wis + 2 * k2);
        acc = f2fma(xw, wj2, acc);
    }
    float2 q = f2unpack(acc);
    float dot = q.x + q.y;
    float pd = fmaxf(g_wsq[i] + g_wsq[j] - 2.0f * dot, 0.0f);

    float sep = ep, swl = ep * pd;
#pragma unroll
    for (int o = 16; o; o >>= 1) {
        sep += __shfl_xor_sync(0xffffffffu, sep, o);
        swl += __shfl_xor_sync(0xffffffffu, swl, o);
    }
    if (lane == 0) { red_ep[warp] = sep; red_wl[warp] = swl; }
    __syncthreads();
    if (j == 0) {
        float rs = 0.0f, rw = 0.0f;
#pragma unroll
        for (int w = 0; w < 8; w++) { rs += red_ep[w]; rw += red_wl[w]; }
        g_ep_rowsum[i] = rs;
        g_wl_rowsum[i] = rw;
        g_factor[i] = 1.0f + TOPO_C * (rs / (float)(M_N - 1));
    }
}

// ---------------- K3: fused distances + soft-rank ----------------
// 512 blocks x 256 threads; each block owns 8 data rows.
// Phase A: GEMM vs Wtp (direct LDG, no staging/barriers), dists -> shared.
// Phase B: per-row softmax-style rank with batched reciprocals + f32x2.
#define RPB 8

__global__ void __launch_bounds__(256) k_fused(const float* __restrict__ X) {
    const int t = threadIdx.x;
    const int lane = t & 31, warp = t >> 5;
    const int b0 = blockIdx.x * RPB;

    __shared__ __align__(16) float Xs[RPB][260];
    __shared__ __align__(16) float us[RPB][256];   // u table (interleaved) -> reused for contribs
    __shared__ __align__(16) float dts[RPB][256];  // distance tile
    __shared__ float dmx[RPB];

    // load X tile (coalesced, conflict-free)
#pragma unroll
    for (int p = 0; p < 8; p++) {
        int q = t + p * 256;
        int r = q >> 8, k = q & 255;
        Xs[r][k] = X[(size_t)(b0 + r) * D_N + k];
    }
    __syncthreads();

    // ---- GEMM: micro 2 rows x 4 cols, k packed in pairs ----
    const int ty = t >> 6;        // 0..3
    const int tx = t & 63;        // 0..63
    const int r0 = ty * 2;
    const int m0 = tx * 4;

    u64 acc[2][4];
#pragma unroll
    for (int i = 0; i < 2; i++)
#pragma unroll
        for (int jj = 0; jj < 4; jj++) acc[i][jj] = 0ull;

    const float4* wbase = (const float4*)(g_Wtp + m0 * 2);
#pragma unroll 4
    for (int kk4 = 0; kk4 < 64; kk4++) {
        // W: k-pairs (2kk4) and (2kk4+1) for m0..m0+3
        float4 wa = wbase[(2 * kk4) * 128];       // k01, m0..m0+1
        float4 wb = wbase[(2 * kk4) * 128 + 1];   // k01, m0+2..m0+3
        float4 wc = wbase[(2 * kk4 + 1) * 128];   // k23, m0..m0+1
        float4 wd = wbase[(2 * kk4 + 1) * 128 + 1];
        const u64* w01 = (const u64*)&wa;  // [0]=m0, [1]=m0+1
        const u64* w01b = (const u64*)&wb;
        const u64* w23 = (const u64*)&wc;
        const u64* w23b = (const u64*)&wd;
#pragma unroll
        for (int i = 0; i < 2; i++) {
            ulonglong2 xv = *(const ulonglong2*)&Xs[r0 + i][kk4 * 4];
            acc[i][0] = f2fma(xv.x, w01[0], acc[i][0]);
            acc[i][1] = f2fma(xv.x, w01[1], acc[i][1]);
            acc[i][2] = f2fma(xv.x, w01b[0], acc[i][2]);
            acc[i][3] = f2fma(xv.x, w01b[1], acc[i][3]);
            acc[i][0] = f2fma(xv.y, w23[0], acc[i][0]);
            acc[i][1] = f2fma(xv.y, w23[1], acc[i][1]);
            acc[i][2] = f2fma(xv.y, w23b[0], acc[i][2]);
            acc[i][3] = f2fma(xv.y, w23b[1], acc[i][3]);
        }
    }

    // distances -> shared
    float wsq4[4];
#pragma unroll
    for (int jj = 0; jj < 4; jj++) wsq4[jj] = g_wsq[m0 + jj];
#pragma unroll
    for (int i = 0; i < 2; i++) {
        float xq = g_xsq[b0 + r0 + i];
        float dv[4];
#pragma unroll
        for (int jj = 0; jj < 4; jj++) {
            float2 qq = f2unpack(acc[i][jj]);
            float dot = qq.x + qq.y;
            dv[jj] = sqrtf(fmaxf(xq + wsq4[jj] - 2.0f * dot, 0.0f));
        }
        *(float4*)&dts[r0 + i][m0] = make_float4(dv[0], dv[1], dv[2], dv[3]);
    }
    __syncthreads();

    // ---- row max: warp w reduces row w ----
    {
        float mx = -1.0f;
#pragma unroll
        for (int p = 0; p < 8; p++) mx = fmaxf(mx, dts[warp][lane + 32 * p]);
#pragma unroll
        for (int o = 16; o; o >>= 1) mx = fmaxf(mx, __shfl_xor_sync(0xffffffffu, mx, o));
        if (lane == 0) dmx[warp] = mx;
    }
    __syncthreads();

    // ---- u table: u[r][i] = exp((d-dmax)/tau), rescaled by 2^30 ----
    float u_reg[RPB], d_reg[RPB];
#pragma unroll
    for (int r = 0; r < RPB; r++) {
        float d = dts[r][t];
        d_reg[r] = d;
        float arg = fmaxf((d - dmx[r]) * TAU_INV_LOG2E, -60.0f) + 30.0f;
        float u = exp2f(arg);
        u_reg[r] = u;
        us[r][2 * (t & 127) + (t >> 7)] = u;  // interleaved for packed reads
    }
    float fac = g_factor[t];
    __syncthreads();

    // ---- main rank loop: 1 MUFU.RCP per 4 pairs, f32x2 packed ----
    float contrib[RPB];
    for (int r = 0; r < RPB; r++) {
        float ui = u_reg[r];
        u64 ui2 = f2dup(ui);
        u64 acc2 = 0ull;
        const ulonglong2* uv = (const ulonglong2*)&us[r][0];
#pragma unroll 8
        for (int it = 0; it < 32; it++) {
            ulonglong2 w0 = uv[2 * it];
            ulonglong2 w1 = uv[2 * it + 1];
            u64 a  = f2add(ui2, w0.x);
            u64 bb = f2add(ui2, w0.y);
            u64 c  = f2add(ui2, w1.x);
            u64 e  = f2add(ui2, w1.y);
            u64 ab = f2mul(a, bb);
            u64 ce = f2mul(c, e);
            u64 prod = f2mul(ab, ce);
            float2 pu = f2unpack(prod);
            u64 rr = f2pack(frcp(pu.x), frcp(pu.y));
            u64 apb = f2add(a, bb);
            u64 cpe = f2add(c, e);
            u64 num = f2mul(apb, ce);
            num = f2fma(cpe, ab, num);
            acc2 = f2fma(num, rr, acc2);
        }
        float2 av = f2unpack(acc2);
        float ssum = ui * (av.x + av.y);     // includes diagonal 0.5
        float srm1 = ssum - 0.5f;
        float neigh = exp2f(-srm1 * LAM_INV_LOG2E);
        contrib[r] = neigh * d_reg[r] * fac;
    }
    __syncthreads();

    // ---- per-row contrib reduction (reuse us buffer) ----
#pragma unroll
    for (int r = 0; r < RPB; r++) us[r][t] = contrib[r];
    __syncthreads();
    {
        float s = 0.0f;
#pragma unroll
        for (int p = 0; p < 8; p++) s += us[warp][lane + 32 * p];
#pragma unroll
        for (int o = 16; o; o >>= 1) s += __shfl_xor_sync(0xffffffffu, s, o);
        if (lane == 0) g_part[b0 + warp] = s;
    }
}

// ---------------- K4: final fixed-order reduction + loss assembly ----------------
__global__ void __launch_bounds__(256) k_final(float* __restrict__ out) {
    const int t = threadIdx.x;
    const int lane = t & 31, warp = t >> 5;
    __shared__ float red[8][4];

    const float4* gp4 = (const float4*)g_part;
    float sd = 0.0f;
#pragma unroll
    for (int p = 0; p < 4; p++) {
        float4 v = gp4[t + 256 * p];
        sd += (v.x + v.y) + (v.z + v.w);
    }
    float se = g_ep_rowsum[t];
    float sw = g_wl_rowsum[t];

#pragma unroll
    for (int o = 16; o; o >>= 1) {
        sd += __shfl_xor_sync(0xffffffffu, sd, o);
        se += __shfl_xor_sync(0xffffffffu, se, o);
        sw += __shfl_xor_sync(0xffffffffu, sw, o);
    }
    if (lane == 0) { red[warp][0] = sd; red[warp][1] = se; red[warp][2] = sw; }
    __syncthreads();
    if (t == 0) {
        float data_sum = 0.0f, ep_sum = 0.0f, wl_sum = 0.0f;
#pragma unroll
        for (int w = 0; w < 8; w++) {
            data_sum += red[w][0];
            ep_sum += red[w][1];
            wl_sum += red[w][2];
        }
        float data_term = data_sum * (1.0f / (float)(B_N * M_N));
        float weighted_len = wl_sum / (ep_sum + 1e-8f);
        float sparsity = ep_sum * (1.0f / (float)(M_N * M_N));
        out[0] = data_term + LEN_C * weighted_len + SP_C * sparsity;
    }
}

// ---------------- launch ----------------
extern "C" void kernel_launch(void* const* d_in, const int* in_sizes, int n_in,
                              void* d_out, int out_size) {
    const float* data = (const float*)d_in[0];     // [4096, 256]
    const float* weights = (const float*)d_in[1];  // [256, 256]
    const float* elog = (const float*)d_in[2];     // [256, 256]
    float* out = (float*)d_out;

    k_pre1<<<528, 256>>>(data, weights);
    k_pre2<<<M_N, 256>>>(weights, elog);
    k_fused<<<B_N / RPB, 256>>>(data);
    k_final<<<1, 256>>>(out);
}

// round 7
// speedup vs baseline: 1.0457x; 1.0457x over previous
#include <cuda_runtime.h>
#include <cuda_bf16.h>
#include <math.h>

// Problem constants (fixed by setup_inputs)
#define B_N 4096
#define M_N 256
#define D_N 256

#define TAU_INV_LOG2E 7.213475204444817f   // log2(e)/0.2
#define LAM_INV_LOG2E 0.18033688011112043f // log2(e)/8
#define TOPO_C 0.5f
#define LEN_C 0.01f
#define SP_C 0.001f

typedef unsigned long long u64;

// ---------------- packed f32x2 helpers (sm_103a) ----------------
__device__ __forceinline__ u64 f2add(u64 a, u64 b) {
    u64 o; asm("add.rn.f32x2 %0, %1, %2;" : "=l"(o) : "l"(a), "l"(b)); return o;
}
__device__ __forceinline__ u64 f2mul(u64 a, u64 b) {
    u64 o; asm("mul.rn.f32x2 %0, %1, %2;" : "=l"(o) : "l"(a), "l"(b)); return o;
}
__device__ __forceinline__ u64 f2fma(u64 a, u64 b, u64 c) {
    u64 o; asm("fma.rn.f32x2 %0, %1, %2, %3;" : "=l"(o) : "l"(a), "l"(b), "l"(c)); return o;
}
__device__ __forceinline__ u64 f2dup(float x) {
    u64 o; asm("mov.b64 %0, {%1, %1};" : "=l"(o) : "f"(x)); return o;
}
__device__ __forceinline__ u64 f2pack(float x, float y) {
    u64 o; asm("mov.b64 %0, {%1, %2};" : "=l"(o) : "f"(x), "f"(y)); return o;
}
__device__ __forceinline__ float2 f2unpack(u64 v) {
    float2 o; asm("mov.b64 {%0, %1}, %2;" : "=f"(o.x), "=f"(o.y) : "l"(v)); return o;
}
__device__ __forceinline__ float frcp(float x) {
    float r; asm("rcp.approx.ftz.f32 %0, %1;" : "=f"(r) : "f"(x)); return r;
}

// ---------------- device scratch (no allocations allowed) ----------------
__device__ float g_Wtp[128 * 512];        // W transposed, k-pair-major: [k2][m][2], 256KB
__device__ float g_xsq[B_N];              // ||x_b||^2
__device__ float g_wsq[M_N];              // ||w_m||^2
__device__ float g_factor[M_N];           // 1 + TOPO*degree[m]
__device__ float g_ep_rowsum[M_N];
__device__ float g_wl_rowsum[M_N];
__device__ float g_part[B_N];             // per-row data_term partials
__device__ unsigned int g_ctr;            // last-block ticket

// ---------------- K1: x-norms + w-norms + W transpose + ctr reset ----------------
__global__ void __launch_bounds__(256) k_pre1(const float* __restrict__ X,
                                              const float* __restrict__ W) {
    const int t = threadIdx.x;
    const int lane = t & 31, warp = t >> 5;
    __shared__ float Ws[16][260];

    if (blockIdx.x == 0 && t == 0) g_ctr = 0u;

    if (blockIdx.x < 512) {
        int row = blockIdx.x * 8 + warp;
        const float4* r4 = (const float4*)(X + (size_t)row * D_N);
        float s = 0.0f;
#pragma unroll
        for (int k = 0; k < 2; k++) {
            float4 v = r4[lane + 32 * k];
            s = fmaf(v.x, v.x, s); s = fmaf(v.y, v.y, s);
            s = fmaf(v.z, v.z, s); s = fmaf(v.w, v.w, s);
        }
#pragma unroll
        for (int o = 16; o; o >>= 1) s += __shfl_xor_sync(0xffffffffu, s, o);
        if (lane == 0) g_xsq[row] = s;
        return;
    }

    const int m0 = (blockIdx.x - 512) * 16;
#pragma unroll
    for (int p = 0; p < 16; p++) {
        int q = t + p * 256;
        int r = q >> 8, k = q & 255;
        Ws[r][k] = W[(size_t)(m0 + r) * D_N + k];
    }
    __syncthreads();

#pragma unroll
    for (int rr = 0; rr < 2; rr++) {
        int row = warp * 2 + rr;
        float s = 0.0f;
#pragma unroll
        for (int p = 0; p < 8; p++) {
            float v = Ws[row][lane + 32 * p];
            s = fmaf(v, v, s);
        }
#pragma unroll
        for (int o = 16; o; o >>= 1) s += __shfl_xor_sync(0xffffffffu, s, o);
        if (lane == 0) g_wsq[m0 + row] = s;
    }

#pragma unroll
    for (int p = 0; p < 16; p++) {
        int k2 = p * 8 + warp;       // 0..127
        int mloc = lane >> 1, e = lane & 1;
        g_Wtp[k2 * 512 + (m0 + mloc) * 2 + e] = Ws[mloc][k2 * 2 + e];
    }
}

// ---------------- K2: edges, 4 i-rows per block, coalesced Wtp columns ----------------
__global__ void __launch_bounds__(256) k_edges(const float* __restrict__ W,
                                               const float* __restrict__ E) {
    const int i0 = blockIdx.x * 4;
    const int j = threadIdx.x;
    const int lane = j & 31, warp = j >> 5;

    __shared__ __align__(16) float wis[4][256];
    __shared__ float red_ep[4][8];
    __shared__ float red_wl[4][8];

#pragma unroll
    for (int p = 0; p < 4; p++) {
        int q = j + p * 256;
        int r = q >> 8, k = q & 255;
        wis[r][k] = W[(size_t)(i0 + r) * D_N + k];
    }
    __syncthreads();

    // 4 dot products vs W column j (coalesced LDG.64 over Wtp)
    u64 acc[4] = {0ull, 0ull, 0ull, 0ull};
    const float* wtpj = g_Wtp + j * 2;
#pragma unroll 4
    for (int k2 = 0; k2 < 128; k2++) {
        u64 wj2 = *(const u64*)(wtpj + k2 * 512);
#pragma unroll
        for (int i = 0; i < 4; i++) {
            u64 xw = *(const u64*)&wis[i][2 * k2];
            acc[i] = f2fma(xw, wj2, acc[i]);
        }
    }

    float wsqj = g_wsq[j];
#pragma unroll
    for (int i = 0; i < 4; i++) {
        int ig = i0 + i;
        float2 q = f2unpack(acc[i]);
        float dot = q.x + q.y;
        float pd = fmaxf(g_wsq[ig] + wsqj - 2.0f * dot, 0.0f);

        float lij = 0.5f * (E[ig * M_N + j] + E[j * M_N + ig]);
        float ep = __fdividef(1.0f, 1.0f + __expf(-lij));
        if (j == ig) ep = 0.0f;

        float sep = ep, swl = ep * pd;
#pragma unroll
        for (int o = 16; o; o >>= 1) {
            sep += __shfl_xor_sync(0xffffffffu, sep, o);
            swl += __shfl_xor_sync(0xffffffffu, swl, o);
        }
        if (lane == 0) { red_ep[i][warp] = sep; red_wl[i][warp] = swl; }
    }
    __syncthreads();
    if (j < 4) {
        float rs = 0.0f, rw = 0.0f;
#pragma unroll
        for (int w = 0; w < 8; w++) { rs += red_ep[j][w]; rw += red_wl[j][w]; }
        int ig = i0 + j;
        g_ep_rowsum[ig] = rs;
        g_wl_rowsum[ig] = rw;
        g_factor[ig] = 1.0f + TOPO_C * (rs / (float)(M_N - 1));
    }
}

// ---------------- K3: fused distances + soft-rank + last-block final ----------------
// 512 blocks x 256 threads, 8 data rows per block.
// Shared = exactly 48KB: Xs 8KB + dts 8KB + pool 32KB (Wc chunks, then u-table).
#define RPB 8

__global__ void __launch_bounds__(256, 4) k_fused(const float* __restrict__ X,
                                                  float* __restrict__ out) {
    const int t = threadIdx.x;
    const int lane = t & 31, warp = t >> 5;
    const int b0 = blockIdx.x * RPB;

    __shared__ __align__(16) float Xs[RPB][256];
    __shared__ __align__(16) float dts[RPB][256];
    __shared__ __align__(16) float pool[8192];   // Wc: 16 k2 x 512; later us[8][256]

    // ---- load X tile (coalesced float4) ----
#pragma unroll
    for (int p = 0; p < 2; p++) {
        int q = t + p * 256;          // float4 index, 0..511
        int r = q >> 6, c4 = q & 63;
        *(float4*)&Xs[r][c4 * 4] = ((const float4*)X)[(size_t)(b0 + r) * 64 + c4];
    }
    __syncthreads();

    // ---- GEMM: 2 rows x 4 m per thread; W staged in shared chunks ----
    const int ty = t >> 6;            // 0..3 -> rows ty*2, ty*2+1
    const int tx = t & 63;            // m in {tx, tx+64, tx+128, tx+192}
    const int r0 = ty * 2;

    u64 acc[2][4];
#pragma unroll
    for (int i = 0; i < 2; i++)
#pragma unroll
        for (int q = 0; q < 4; q++) acc[i][q] = 0ull;

    for (int chunk = 0; chunk < 8; chunk++) {
        // stage 16 k2-rows (32KB) of Wtp
        const float4* src = (const float4*)(g_Wtp + chunk * 8192);
#pragma unroll
        for (int p = 0; p < 8; p++) {
            int idx = t + p * 256;
            ((float4*)pool)[idx] = src[idx];
        }
        __syncthreads();

#pragma unroll
        for (int k2 = 0; k2 < 16; k2 += 2) {
            int kg = (chunk * 16 + k2) * 2;   // float index into Xs row (16B aligned)
            u64 w0[4], w1[4];
#pragma unroll
            for (int q = 0; q < 4; q++) {
                w0[q] = *(const u64*)&pool[k2 * 512 + (tx + 64 * q) * 2];
                w1[q] = *(const u64*)&pool[(k2 + 1) * 512 + (tx + 64 * q) * 2];
            }
#pragma unroll
            for (int i = 0; i < 2; i++) {
                ulonglong2 xv = *(const ulonglong2*)&Xs[r0 + i][kg];
#pragma unroll
                for (int q = 0; q < 4; q++) {
                    acc[i][q] = f2fma(xv.x, w0[q], acc[i][q]);
                    acc[i][q] = f2fma(xv.y, w1[q], acc[i][q]);
                }
            }
        }
        __syncthreads();
    }

    // ---- distances -> dts ----
    float wsq4[4];
#pragma unroll
    for (int q = 0; q < 4; q++) wsq4[q] = g_wsq[tx + 64 * q];
#pragma unroll
    for (int i = 0; i < 2; i++) {
        float xq = g_xsq[b0 + r0 + i];
#pragma unroll
        for (int q = 0; q < 4; q++) {
            float2 dd = f2unpack(acc[i][q]);
            float dot = dd.x + dd.y;
            dts[r0 + i][tx + 64 * q] = sqrtf(fmaxf(xq + wsq4[q] - 2.0f * dot, 0.0f));
        }
    }
    __syncthreads();

    // ---- d_reg + row max (warp w owns row w) ----
    float d_reg[RPB];
#pragma unroll
    for (int r = 0; r < RPB; r++) d_reg[r] = dts[r][t];

    float mx = -1.0f;
#pragma unroll
    for (int p = 0; p < 8; p++) mx = fmaxf(mx, dts[warp][lane + 32 * p]);
#pragma unroll
    for (int o = 16; o; o >>= 1) mx = fmaxf(mx, __shfl_xor_sync(0xffffffffu, mx, o));
    __syncthreads();                  // all dts reads done before dmx overwrite
    if (lane == 0) dts[0][warp] = mx; // dmx[r] lives at dts[0][r]
    __syncthreads();

    // ---- u table (rescaled by 2^30; ratio-invariant) ----
    float fac = g_factor[t];
    float u_reg[RPB];
#pragma unroll
    for (int r = 0; r < RPB; r++) {
        float arg = fmaxf((d_reg[r] - dts[0][r]) * TAU_INV_LOG2E, -60.0f) + 30.0f;
        float u = exp2f(arg);
        u_reg[r] = u;
        pool[r * 256 + 2 * (t & 127) + (t >> 7)] = u;  // interleaved
    }
    __syncthreads();

    // ---- rank loops: 1 MUFU.RCP per 4 pairs, f32x2 packed ----
#pragma unroll 1
    for (int r = 0; r < RPB; r++) {
        float ui = u_reg[r];
        u64 ui2 = f2dup(ui);
        u64 acc2 = 0ull;
        const ulonglong2* uv = (const ulonglong2*)&pool[r * 256];
#pragma unroll 8
        for (int it = 0; it < 32; it++) {
            ulonglong2 w0 = uv[2 * it];
            ulonglong2 w1 = uv[2 * it + 1];
            u64 a  = f2add(ui2, w0.x);
            u64 bb = f2add(ui2, w0.y);
            u64 c  = f2add(ui2, w1.x);
            u64 e  = f2add(ui2, w1.y);
            u64 ab = f2mul(a, bb);
            u64 ce = f2mul(c, e);
            u64 prod = f2mul(ab, ce);
            float2 pu = f2unpack(prod);
            u64 rr = f2pack(frcp(pu.x), frcp(pu.y));
            u64 apb = f2add(a, bb);
            u64 cpe = f2add(c, e);
            u64 num = f2mul(apb, ce);
            num = f2fma(cpe, ab, num);
            acc2 = f2fma(num, rr, acc2);
        }
        float2 av = f2unpack(acc2);
        float ssum = ui * (av.x + av.y);       // includes diagonal 0.5
        float neigh = exp2f(-(ssum - 0.5f) * LAM_INV_LOG2E);
        dts[r][t] = neigh * d_reg[r] * fac;    // contrib (own column only)
    }
    __syncthreads();

    // ---- per-row contrib reduction ----
    {
        float s = 0.0f;
#pragma unroll
        for (int p = 0; p < 8; p++) s += dts[warp][lane + 32 * p];
#pragma unroll
        for (int o = 16; o; o >>= 1) s += __shfl_xor_sync(0xffffffffu, s, o);
        if (lane == 0) g_part[b0 + warp] = s;
    }

    // ---- last block does the final loss assembly ----
    __threadfence();
    __syncthreads();
    if (t == 0) ((unsigned int*)pool)[0] = atomicAdd(&g_ctr, 1u);
    __syncthreads();
    if (((unsigned int*)pool)[0] != (unsigned int)(gridDim.x - 1)) return;

    float sd = 0.0f;
    const float4* gp4 = (const float4*)g_part;
#pragma unroll
    for (int p = 0; p < 4; p++) {
        float4 v = gp4[t + 256 * p];
        sd += (v.x + v.y) + (v.z + v.w);
    }
    float se = g_ep_rowsum[t];
    float sw = g_wl_rowsum[t];
#pragma unroll
    for (int o = 16; o; o >>= 1) {
        sd += __shfl_xor_sync(0xffffffffu, sd, o);
        se += __shfl_xor_sync(0xffffffffu, se, o);
        sw += __shfl_xor_sync(0xffffffffu, sw, o);
    }
    if (lane == 0) {
        pool[8 + warp] = sd;
        pool[16 + warp] = se;
        pool[24 + warp] = sw;
    }
    __syncthreads();
    if (t == 0) {
        float data_sum = 0.0f, ep_sum = 0.0f, wl_sum = 0.0f;
#pragma unroll
        for (int w = 0; w < 8; w++) {
            data_sum += pool[8 + w];
            ep_sum += pool[16 + w];
            wl_sum += pool[24 + w];
        }
        float data_term = data_sum * (1.0f / (float)(B_N * M_N));
        float weighted_len = wl_sum / (ep_sum + 1e-8f);
        float sparsity = ep_sum * (1.0f / (float)(M_N * M_N));
        out[0] = data_term + LEN_C * weighted_len + SP_C * sparsity;
    }
}

// ---------------- launch ----------------
extern "C" void kernel_launch(void* const* d_in, const int* in_sizes, int n_in,
                              void* d_out, int out_size) {
    const float* data = (const float*)d_in[0];     // [4096, 256]
    const float* weights = (const float*)d_in[1];  // [256, 256]
    const float* elog = (const float*)d_in[2];     // [256, 256]
    float* out = (float*)d_out;

    k_pre1<<<528, 256>>>(data, weights);
    k_edges<<<M_N / 4, 256>>>(weights, elog);
    k_fused<<<B_N / RPB, 256>>>(data, out);
}

// round 8
// speedup vs baseline: 1.1625x; 1.1117x over previous
#include <cuda_runtime.h>
#include <cuda_bf16.h>
#include <math.h>

// Problem constants (fixed by setup_inputs)
#define B_N 4096
#define M_N 256
#define D_N 256

#define TAU_INV_LOG2E 7.213475204444817f   // log2(e)/0.2
#define LAM_INV_LOG2E 0.18033688011112043f // log2(e)/8
#define TOPO_C 0.5f
#define LEN_C 0.01f
#define SP_C 0.001f

typedef unsigned long long u64;

// ---------------- packed f32x2 helpers (sm_103a) ----------------
__device__ __forceinline__ u64 f2add(u64 a, u64 b) {
    u64 o; asm("add.rn.f32x2 %0, %1, %2;" : "=l"(o) : "l"(a), "l"(b)); return o;
}
__device__ __forceinline__ u64 f2mul(u64 a, u64 b) {
    u64 o; asm("mul.rn.f32x2 %0, %1, %2;" : "=l"(o) : "l"(a), "l"(b)); return o;
}
__device__ __forceinline__ u64 f2fma(u64 a, u64 b, u64 c) {
    u64 o; asm("fma.rn.f32x2 %0, %1, %2, %3;" : "=l"(o) : "l"(a), "l"(b), "l"(c)); return o;
}
__device__ __forceinline__ u64 f2dup(float x) {
    u64 o; asm("mov.b64 %0, {%1, %1};" : "=l"(o) : "f"(x)); return o;
}
__device__ __forceinline__ u64 f2pack(float x, float y) {
    u64 o; asm("mov.b64 %0, {%1, %2};" : "=l"(o) : "f"(x), "f"(y)); return o;
}
__device__ __forceinline__ float2 f2unpack(u64 v) {
    float2 o; asm("mov.b64 {%0, %1}, %2;" : "=f"(o.x), "=f"(o.y) : "l"(v)); return o;
}
__device__ __forceinline__ float frcp(float x) {
    float r; asm("rcp.approx.ftz.f32 %0, %1;" : "=f"(r) : "f"(x)); return r;
}

// ---------------- device scratch (no allocations allowed) ----------------
__device__ float g_Wtp[128 * 512];        // W transposed, k-pair-major: [k2][m][2], 256KB
__device__ float g_dist[B_N * M_N];       // 4 MB
__device__ float g_xsq[B_N];
__device__ float g_wsq[M_N];
__device__ float g_factor[M_N];
__device__ float g_ep_rowsum[M_N];
__device__ float g_wl_rowsum[M_N];
__device__ float g_part[B_N];
__device__ unsigned int g_ctr;

// ---------------- K1: x-norms (high MLP) + w-norms + W transpose + ctr reset ----------------
// blocks 0..127: 32 X rows each (8 lanes/row, 8 independent float4 loads per thread)
// blocks 128..143: 16 W rows each: wsq + transpose into g_Wtp
__global__ void __launch_bounds__(256) k_pre1(const float* __restrict__ X,
                                              const float* __restrict__ W) {
    const int t = threadIdx.x;
    const int lane = t & 31, warp = t >> 5;

    if (blockIdx.x == 0 && t == 0) g_ctr = 0u;

    if (blockIdx.x < 128) {
        int row = blockIdx.x * 32 + (t >> 3);
        int sub = t & 7;
        const float4* r4 = (const float4*)(X + (size_t)row * D_N);
        float s = 0.0f;
#pragma unroll
        for (int k = 0; k < 8; k++) {
            float4 v = r4[sub + 8 * k];
            s = fmaf(v.x, v.x, s); s = fmaf(v.y, v.y, s);
            s = fmaf(v.z, v.z, s); s = fmaf(v.w, v.w, s);
        }
#pragma unroll
        for (int o = 4; o; o >>= 1) s += __shfl_xor_sync(0xffffffffu, s, o);
        if (sub == 0) g_xsq[row] = s;
        return;
    }

    __shared__ float Ws[16][260];
    const int m0 = (blockIdx.x - 128) * 16;
#pragma unroll
    for (int p = 0; p < 16; p++) {
        int q = t + p * 256;
        int r = q >> 8, k = q & 255;
        Ws[r][k] = W[(size_t)(m0 + r) * D_N + k];
    }
    __syncthreads();

#pragma unroll
    for (int rr = 0; rr < 2; rr++) {
        int row = warp * 2 + rr;
        float s = 0.0f;
#pragma unroll
        for (int p = 0; p < 8; p++) {
            float v = Ws[row][lane + 32 * p];
            s = fmaf(v, v, s);
        }
#pragma unroll
        for (int o = 16; o; o >>= 1) s += __shfl_xor_sync(0xffffffffu, s, o);
        if (lane == 0) g_wsq[m0 + row] = s;
    }

#pragma unroll
    for (int p = 0; p < 16; p++) {
        int k2 = p * 8 + warp;       // 0..127
        int mloc = lane >> 1, e = lane & 1;
        g_Wtp[k2 * 512 + (m0 + mloc) * 2 + e] = Ws[mloc][k2 * 2 + e];
    }
}

// ---------------- K2: edges, 4 i-rows per block, coalesced Wtp columns ----------------
__global__ void __launch_bounds__(256) k_edges(const float* __restrict__ W,
                                               const float* __restrict__ E) {
    const int i0 = blockIdx.x * 4;
    const int j = threadIdx.x;
    const int lane = j & 31, warp = j >> 5;

    __shared__ __align__(16) float wis[4][256];
    __shared__ float red_ep[4][8];
    __shared__ float red_wl[4][8];

#pragma unroll
    for (int p = 0; p < 4; p++) {
        int q = j + p * 256;
        int r = q >> 8, k = q & 255;
        wis[r][k] = W[(size_t)(i0 + r) * D_N + k];
    }
    __syncthreads();

    u64 acc[4] = {0ull, 0ull, 0ull, 0ull};
    const float* wtpj = g_Wtp + j * 2;
#pragma unroll 4
    for (int k2 = 0; k2 < 128; k2++) {
        u64 wj2 = *(const u64*)(wtpj + k2 * 512);
#pragma unroll
        for (int i = 0; i < 4; i++) {
            u64 xw = *(const u64*)&wis[i][2 * k2];
            acc[i] = f2fma(xw, wj2, acc[i]);
        }
    }

    float wsqj = g_wsq[j];
#pragma unroll
    for (int i = 0; i < 4; i++) {
        int ig = i0 + i;
        float2 q = f2unpack(acc[i]);
        float dot = q.x + q.y;
        float pd = fmaxf(g_wsq[ig] + wsqj - 2.0f * dot, 0.0f);

        float lij = 0.5f * (E[ig * M_N + j] + E[j * M_N + ig]);
        float ep = __fdividef(1.0f, 1.0f + __expf(-lij));
        if (j == ig) ep = 0.0f;

        float sep = ep, swl = ep * pd;
#pragma unroll
        for (int o = 16; o; o >>= 1) {
            sep += __shfl_xor_sync(0xffffffffu, sep, o);
            swl += __shfl_xor_sync(0xffffffffu, swl, o);
        }
        if (lane == 0) { red_ep[i][warp] = sep; red_wl[i][warp] = swl; }
    }
    __syncthreads();
    if (j < 4) {
        float rs = 0.0f, rw = 0.0f;
#pragma unroll
        for (int w = 0; w < 8; w++) { rs += red_ep[j][w]; rw += red_wl[j][w]; }
        int ig = i0 + j;
        g_ep_rowsum[ig] = rs;
        g_wl_rowsum[ig] = rw;
        g_factor[ig] = 1.0f + TOPO_C * (rs / (float)(M_N - 1));
    }
}

// ---------------- K3: distance GEMM ----------------
// 512 blocks x 128 threads; 8 rows/block; micro = 8 rows x 2 m per thread.
// W reuse x8 -> 0.25 wf/FFMA2; X loads are warp-broadcast -> smem balanced.
__global__ void __launch_bounds__(128) k_gemm(const float* __restrict__ X) {
    const int t = threadIdx.x;          // 0..127
    const int b0 = blockIdx.x * 8;
    const int m1 = t, m2 = t + 128;

    __shared__ __align__(16) float Xs[8][256];   // 8KB
    __shared__ __align__(16) float pool[8192];   // 32KB W chunk (16 k2-rows)

    // load X tile: 512 float4 / 128 threads
#pragma unroll
    for (int p = 0; p < 4; p++) {
        int q = t + p * 128;            // float4 idx 0..511
        int r = q >> 6, c4 = q & 63;
        *(float4*)&Xs[r][c4 * 4] = ((const float4*)X)[(size_t)(b0 + r) * 64 + c4];
    }
    __syncthreads();

    u64 acc[8][2];
#pragma unroll
    for (int r = 0; r < 8; r++) { acc[r][0] = 0ull; acc[r][1] = 0ull; }

    for (int chunk = 0; chunk < 8; chunk++) {
        const float4* src = (const float4*)(g_Wtp + chunk * 8192);
#pragma unroll
        for (int p = 0; p < 16; p++) {
            int idx = t + p * 128;
            ((float4*)pool)[idx] = src[idx];
        }
        __syncthreads();

#pragma unroll
        for (int k2 = 0; k2 < 16; k2 += 2) {
            u64 w0a = *(const u64*)&pool[k2 * 512 + m1 * 2];
            u64 w0b = *(const u64*)&pool[k2 * 512 + m2 * 2];
            u64 w1a = *(const u64*)&pool[(k2 + 1) * 512 + m1 * 2];
            u64 w1b = *(const u64*)&pool[(k2 + 1) * 512 + m2 * 2];
            int kg = (chunk * 16 + k2) * 2;     // 16B-aligned float idx
#pragma unroll
            for (int r = 0; r < 8; r++) {
                ulonglong2 xv = *(const ulonglong2*)&Xs[r][kg];  // broadcast
                acc[r][0] = f2fma(xv.x, w0a, acc[r][0]);
                acc[r][1] = f2fma(xv.x, w0b, acc[r][1]);
                acc[r][0] = f2fma(xv.y, w1a, acc[r][0]);
                acc[r][1] = f2fma(xv.y, w1b, acc[r][1]);
            }
        }
        __syncthreads();
    }

    float wsq1 = g_wsq[m1], wsq2 = g_wsq[m2];
#pragma unroll
    for (int r = 0; r < 8; r++) {
        float xq = g_xsq[b0 + r];
        float2 da = f2unpack(acc[r][0]);
        float2 db = f2unpack(acc[r][1]);
        float dot1 = da.x + da.y;
        float dot2 = db.x + db.y;
        g_dist[(size_t)(b0 + r) * M_N + m1] = sqrtf(fmaxf(xq + wsq1 - 2.0f * dot1, 0.0f));
        g_dist[(size_t)(b0 + r) * M_N + m2] = sqrtf(fmaxf(xq + wsq2 - 2.0f * dot2, 0.0f));
    }
}

// ---------------- K4: soft-rank (s2/p2 table algebra) + last-block final ----------------
// grid 4096 x 256. Per 4-denominator group: ab = ui^2 + ui*s2 + p2 (2 ops),
// a+b = 2ui + s2 (1 op) -> 10 fma-ops per 8 pairs (was 12). 1 MUFU.RCP per 4 pairs.
__global__ void __launch_bounds__(256) k_rank(float* __restrict__ out) {
    const int b = blockIdx.x;
    const int t = threadIdx.x;
    const int lane = t & 31, warp = t >> 5;

    __shared__ __align__(16) float us[256];        // interleaved u table (128 u64 pairs)
    __shared__ __align__(16) ulonglong2 sp[64];    // sp[g] = {s2_pk, p2_pk}
    __shared__ float red[8];

    float d = g_dist[(size_t)b * M_N + t];

    // row max
    float mx = d;
#pragma unroll
    for (int o = 16; o; o >>= 1) mx = fmaxf(mx, __shfl_xor_sync(0xffffffffu, mx, o));
    if (lane == 0) red[warp] = mx;
    __syncthreads();
    float dmax = red[0];
#pragma unroll
    for (int w = 1; w < 8; w++) dmax = fmaxf(dmax, red[w]);

    // u table (rescaled by 2^30; ratio-invariant)
    float arg = fmaxf((d - dmax) * TAU_INV_LOG2E, -60.0f) + 30.0f;
    float ui = exp2f(arg);
    us[2 * (t & 127) + (t >> 7)] = ui;   // lo half even slots, hi half odd
    __syncthreads();

    // build s2/p2 tables: group g = u64 entries {2g, 2g+1}
    if (t < 64) {
        const u64* u64v = (const u64*)us;
        u64 ua = u64v[2 * t];
        u64 ub = u64v[2 * t + 1];
        ulonglong2 e;
        e.x = f2add(ua, ub);   // s2
        e.y = f2mul(ua, ub);   // p2
        sp[t] = e;
    }
    __syncthreads();

    u64 uipk  = f2dup(ui);
    u64 uisq  = f2mul(uipk, uipk);
    u64 twoui = f2add(uipk, uipk);

    u64 acc = 0ull;
#pragma unroll 8
    for (int it = 0; it < 32; it++) {
        ulonglong2 ga = sp[2 * it];        // broadcast LDS.128
        ulonglong2 gb = sp[2 * it + 1];
        u64 ab = f2fma(uipk, ga.x, f2add(uisq, ga.y));
        u64 ce = f2fma(uipk, gb.x, f2add(uisq, gb.y));
        u64 apb = f2add(twoui, ga.x);
        u64 cpe = f2add(twoui, gb.x);
        u64 prod = f2mul(ab, ce);
        float2 pu = f2unpack(prod);
        u64 rr = f2pack(frcp(pu.x), frcp(pu.y));
        u64 num = f2mul(apb, ce);
        num = f2fma(cpe, ab, num);
        acc = f2fma(num, rr, acc);
    }
    float2 av = f2unpack(acc);
    float ssum = ui * (av.x + av.y);       // includes diagonal 0.5
    float neigh = exp2f(-(ssum - 0.5f) * LAM_INV_LOG2E);
    float contrib = neigh * d * g_factor[t];

#pragma unroll
    for (int o = 16; o; o >>= 1) contrib += __shfl_xor_sync(0xffffffffu, contrib, o);
    __syncthreads();               // red[] (dmax) reads all done
    if (lane == 0) red[warp] = contrib;
    __syncthreads();
    if (t == 0) {
        float s = red[0];
#pragma unroll
        for (int w = 1; w < 8; w++) s += red[w];
        g_part[b] = s;
    }

    // ---- last block: final loss assembly ----
    __shared__ unsigned int ticket;
    __threadfence();
    __syncthreads();
    if (t == 0) ticket = atomicAdd(&g_ctr, 1u);
    __syncthreads();
    if (ticket != (unsigned int)(gridDim.x - 1)) return;

    __shared__ float fin[24];
    float sd = 0.0f;
    const float4* gp4 = (const float4*)g_part;
#pragma unroll
    for (int p = 0; p < 4; p++) {
        float4 v = gp4[t + 256 * p];
        sd += (v.x + v.y) + (v.z + v.w);
    }
    float se = g_ep_rowsum[t];
    float sw = g_wl_rowsum[t];
#pragma unroll
    for (int o = 16; o; o >>= 1) {
        sd += __shfl_xor_sync(0xffffffffu, sd, o);
        se += __shfl_xor_sync(0xffffffffu, se, o);
        sw += __shfl_xor_sync(0xffffffffu, sw, o);
    }
    if (lane == 0) { fin[warp] = sd; fin[8 + warp] = se; fin[16 + warp] = sw; }
    __syncthreads();
    if (t == 0) {
        float data_sum = 0.0f, ep_sum = 0.0f, wl_sum = 0.0f;
#pragma unroll
        for (int w = 0; w < 8; w++) {
            data_sum += fin[w];
            ep_sum += fin[8 + w];
            wl_sum += fin[16 + w];
        }
        float data_term = data_sum * (1.0f / (float)(B_N * M_N));
        float weighted_len = wl_sum / (ep_sum + 1e-8f);
        float sparsity = ep_sum * (1.0f / (float)(M_N * M_N));
        out[0] = data_term + LEN_C * weighted_len + SP_C * sparsity;
    }
}

// ---------------- launch ----------------
extern "C" void kernel_launch(void* const* d_in, const int* in_sizes, int n_in,
                              void* d_out, int out_size) {
    const float* data = (const float*)d_in[0];     // [4096, 256]
    const float* weights = (const float*)d_in[1];  // [256, 256]
    const float* elog = (const float*)d_in[2];     // [256, 256]
    float* out = (float*)d_out;

    k_pre1<<<144, 256>>>(data, weights);
    k_edges<<<M_N / 4, 256>>>(weights, elog);
    k_gemm<<<B_N / 8, 128>>>(data);
    k_rank<<<B_N, 256>>>(out);
}

// round 9
// speedup vs baseline: 1.2463x; 1.0720x over previous
#include <cuda_runtime.h>
#include <cuda_bf16.h>
#include <math.h>

// Problem constants (fixed by setup_inputs)
#define B_N 4096
#define M_N 256
#define D_N 256

#define TAU_INV_LOG2E 7.213475204444817f   // log2(e)/0.2
#define LAM_INV_LOG2E 0.18033688011112043f // log2(e)/8
#define TOPO_C 0.5f
#define LEN_C 0.01f
#define SP_C 0.001f

typedef unsigned long long u64;

// ---------------- packed f32x2 helpers (sm_103a) ----------------
__device__ __forceinline__ u64 f2add(u64 a, u64 b) {
    u64 o; asm("add.rn.f32x2 %0, %1, %2;" : "=l"(o) : "l"(a), "l"(b)); return o;
}
__device__ __forceinline__ u64 f2mul(u64 a, u64 b) {
    u64 o; asm("mul.rn.f32x2 %0, %1, %2;" : "=l"(o) : "l"(a), "l"(b)); return o;
}
__device__ __forceinline__ u64 f2fma(u64 a, u64 b, u64 c) {
    u64 o; asm("fma.rn.f32x2 %0, %1, %2, %3;" : "=l"(o) : "l"(a), "l"(b), "l"(c)); return o;
}
__device__ __forceinline__ u64 f2dup(float x) {
    u64 o; asm("mov.b64 %0, {%1, %1};" : "=l"(o) : "f"(x)); return o;
}
__device__ __forceinline__ u64 f2pack(float x, float y) {
    u64 o; asm("mov.b64 %0, {%1, %2};" : "=l"(o) : "f"(x), "f"(y)); return o;
}
__device__ __forceinline__ float2 f2unpack(u64 v) {
    float2 o; asm("mov.b64 {%0, %1}, %2;" : "=f"(o.x), "=f"(o.y) : "l"(v)); return o;
}
__device__ __forceinline__ float frcp(float x) {
    float r; asm("rcp.approx.ftz.f32 %0, %1;" : "=f"(r) : "f"(x)); return r;
}

// ---------------- device scratch (no allocations allowed) ----------------
__device__ float g_Wtp[128 * 512];        // W transposed, k-pair-major: [k2][m][2], 256KB
__device__ float g_dist[B_N * M_N];       // 4 MB
__device__ float g_xsq[B_N];
__device__ float g_wsq[M_N];
__device__ float g_factor[M_N];
__device__ float g_ep_rowsum[M_N];
__device__ float g_wl_rowsum[M_N];
__device__ float g_part[B_N];
__device__ unsigned int g_ctr;

// ---------------- K1: x-norms + w-norms + W transpose + ctr reset ----------------
__global__ void __launch_bounds__(256) k_pre1(const float* __restrict__ X,
                                              const float* __restrict__ W) {
    const int t = threadIdx.x;
    const int lane = t & 31, warp = t >> 5;

    if (blockIdx.x == 0 && t == 0) g_ctr = 0u;

    if (blockIdx.x < 128) {
        int row = blockIdx.x * 32 + (t >> 3);
        int sub = t & 7;
        const float4* r4 = (const float4*)(X + (size_t)row * D_N);
        float s = 0.0f;
#pragma unroll
        for (int k = 0; k < 8; k++) {
            float4 v = r4[sub + 8 * k];
            s = fmaf(v.x, v.x, s); s = fmaf(v.y, v.y, s);
            s = fmaf(v.z, v.z, s); s = fmaf(v.w, v.w, s);
        }
#pragma unroll
        for (int o = 4; o; o >>= 1) s += __shfl_xor_sync(0xffffffffu, s, o);
        if (sub == 0) g_xsq[row] = s;
        return;
    }

    __shared__ float Ws[16][260];
    const int m0 = (blockIdx.x - 128) * 16;
#pragma unroll
    for (int p = 0; p < 16; p++) {
        int q = t + p * 256;
        int r = q >> 8, k = q & 255;
        Ws[r][k] = W[(size_t)(m0 + r) * D_N + k];
    }
    __syncthreads();

#pragma unroll
    for (int rr = 0; rr < 2; rr++) {
        int row = warp * 2 + rr;
        float s = 0.0f;
#pragma unroll
        for (int p = 0; p < 8; p++) {
            float v = Ws[row][lane + 32 * p];
            s = fmaf(v, v, s);
        }
#pragma unroll
        for (int o = 16; o; o >>= 1) s += __shfl_xor_sync(0xffffffffu, s, o);
        if (lane == 0) g_wsq[m0 + row] = s;
    }

#pragma unroll
    for (int p = 0; p < 16; p++) {
        int k2 = p * 8 + warp;       // 0..127
        int mloc = lane >> 1, e = lane & 1;
        g_Wtp[k2 * 512 + (m0 + mloc) * 2 + e] = Ws[mloc][k2 * 2 + e];
    }
}

// ---------------- K2: edges, 4 i-rows per block, coalesced Wtp columns ----------------
__global__ void __launch_bounds__(256) k_edges(const float* __restrict__ W,
                                               const float* __restrict__ E) {
    const int i0 = blockIdx.x * 4;
    const int j = threadIdx.x;
    const int lane = j & 31, warp = j >> 5;

    __shared__ __align__(16) float wis[4][256];
    __shared__ float red_ep[4][8];
    __shared__ float red_wl[4][8];

#pragma unroll
    for (int p = 0; p < 4; p++) {
        int q = j + p * 256;
        int r = q >> 8, k = q & 255;
        wis[r][k] = W[(size_t)(i0 + r) * D_N + k];
    }
    __syncthreads();

    u64 acc[4] = {0ull, 0ull, 0ull, 0ull};
    const float* wtpj = g_Wtp + j * 2;
#pragma unroll 4
    for (int k2 = 0; k2 < 128; k2++) {
        u64 wj2 = *(const u64*)(wtpj + k2 * 512);
#pragma unroll
        for (int i = 0; i < 4; i++) {
            u64 xw = *(const u64*)&wis[i][2 * k2];
            acc[i] = f2fma(xw, wj2, acc[i]);
        }
    }

    float wsqj = g_wsq[j];
#pragma unroll
    for (int i = 0; i < 4; i++) {
        int ig = i0 + i;
        float2 q = f2unpack(acc[i]);
        float dot = q.x + q.y;
        float pd = fmaxf(g_wsq[ig] + wsqj - 2.0f * dot, 0.0f);

        float lij = 0.5f * (E[ig * M_N + j] + E[j * M_N + ig]);
        float ep = __fdividef(1.0f, 1.0f + __expf(-lij));
        if (j == ig) ep = 0.0f;

        float sep = ep, swl = ep * pd;
#pragma unroll
        for (int o = 16; o; o >>= 1) {
            sep += __shfl_xor_sync(0xffffffffu, sep, o);
            swl += __shfl_xor_sync(0xffffffffu, swl, o);
        }
        if (lane == 0) { red_ep[i][warp] = sep; red_wl[i][warp] = swl; }
    }
    __syncthreads();
    if (j < 4) {
        float rs = 0.0f, rw = 0.0f;
#pragma unroll
        for (int w = 0; w < 8; w++) { rs += red_ep[j][w]; rw += red_wl[j][w]; }
        int ig = i0 + j;
        g_ep_rowsum[ig] = rs;
        g_wl_rowsum[ig] = rw;
        g_factor[ig] = 1.0f + TOPO_C * (rs / (float)(M_N - 1));
    }
}

// ---------------- K3: distance GEMM ----------------
// 256 blocks x 128 threads; 16 rows/block; micro = 16 rows x 2 m per thread.
// W staged in 32KB shared chunks, reused x16 -> staging traffic halved vs 8-row.
#define GR 16

__global__ void __launch_bounds__(128) k_gemm(const float* __restrict__ X) {
    const int t = threadIdx.x;          // 0..127
    const int b0 = blockIdx.x * GR;
    const int m1 = t, m2 = t + 128;

    __shared__ __align__(16) float Xs[GR][256];  // 16KB
    __shared__ __align__(16) float pool[8192];   // 32KB W chunk (16 k2-rows)

    // load X tile: 1024 float4 / 128 threads
#pragma unroll
    for (int p = 0; p < 8; p++) {
        int q = t + p * 128;            // float4 idx 0..1023
        int r = q >> 6, c4 = q & 63;
        *(float4*)&Xs[r][c4 * 4] = ((const float4*)X)[(size_t)(b0 + r) * 64 + c4];
    }
    __syncthreads();

    u64 acc[GR][2];
#pragma unroll
    for (int r = 0; r < GR; r++) { acc[r][0] = 0ull; acc[r][1] = 0ull; }

    for (int chunk = 0; chunk < 8; chunk++) {
        const float4* src = (const float4*)(g_Wtp + chunk * 8192);
#pragma unroll
        for (int p = 0; p < 16; p++) {
            int idx = t + p * 128;
            ((float4*)pool)[idx] = src[idx];
        }
        __syncthreads();

#pragma unroll
        for (int k2 = 0; k2 < 16; k2 += 2) {
            u64 w0a = *(const u64*)&pool[k2 * 512 + m1 * 2];
            u64 w0b = *(const u64*)&pool[k2 * 512 + m2 * 2];
            u64 w1a = *(const u64*)&pool[(k2 + 1) * 512 + m1 * 2];
            u64 w1b = *(const u64*)&pool[(k2 + 1) * 512 + m2 * 2];
            int kg = (chunk * 16 + k2) * 2;     // 16B-aligned float idx
#pragma unroll
            for (int r = 0; r < GR; r++) {
                ulonglong2 xv = *(const ulonglong2*)&Xs[r][kg];  // broadcast
                acc[r][0] = f2fma(xv.x, w0a, acc[r][0]);
                acc[r][1] = f2fma(xv.x, w0b, acc[r][1]);
                acc[r][0] = f2fma(xv.y, w1a, acc[r][0]);
                acc[r][1] = f2fma(xv.y, w1b, acc[r][1]);
            }
        }
        __syncthreads();
    }

    float wsq1 = g_wsq[m1], wsq2 = g_wsq[m2];
#pragma unroll
    for (int r = 0; r < GR; r++) {
        float xq = g_xsq[b0 + r];
        float2 da = f2unpack(acc[r][0]);
        float2 db = f2unpack(acc[r][1]);
        float dot1 = da.x + da.y;
        float dot2 = db.x + db.y;
        g_dist[(size_t)(b0 + r) * M_N + m1] = sqrtf(fmaxf(xq + wsq1 - 2.0f * dot1, 0.0f));
        g_dist[(size_t)(b0 + r) * M_N + m2] = sqrtf(fmaxf(xq + wsq2 - 2.0f * dot2, 0.0f));
    }
}

// ---------------- K4: soft-rank via quartic polynomial + last-block final ----------------
// Group of 4 u's: sum_k ui/(ui+u_k) = ui * P'(ui)/P(ui), P(x) = prod(x+u_k).
// Coefficients (e1..e4, 3e1, 2e2) built once per row; hot loop = two Horner chains
// sharing operand ui2 (operand-reuse friendly) + 1 packed rcp per 8 ordered pairs.
__global__ void __launch_bounds__(256) k_rank(float* __restrict__ out) {
    const int b = blockIdx.x;
    const int t = threadIdx.x;
    const int lane = t & 31, warp = t >> 5;

    __shared__ __align__(16) float us[256];        // interleaved u table (128 u64 pairs)
    __shared__ __align__(16) ulonglong2 tbl[96];   // 32 groups x {e1,e2},{e3,e4},{3e1,2e2}
    __shared__ float red[8];

    float d = g_dist[(size_t)b * M_N + t];

    // row max
    float mx = d;
#pragma unroll
    for (int o = 16; o; o >>= 1) mx = fmaxf(mx, __shfl_xor_sync(0xffffffffu, mx, o));
    if (lane == 0) red[warp] = mx;
    __syncthreads();
    float dmax = red[0];
#pragma unroll
    for (int w = 1; w < 8; w++) dmax = fmaxf(dmax, red[w]);

    // u table (rescaled by 2^30; ratio-invariant). P in [2^-116, 2^124]: safe.
    float arg = fmaxf((d - dmax) * TAU_INV_LOG2E, -60.0f) + 30.0f;
    float ui = exp2f(arg);
    us[2 * (t & 127) + (t >> 7)] = ui;   // u64 slot k = (u_k, u_{k+128})
    __syncthreads();

    // build per-group coefficient tables (32 groups of 4 packed u's)
    if (t < 32) {
        const u64* uv = (const u64*)us;
        u64 u0 = uv[4 * t], u1 = uv[4 * t + 1], u2 = uv[4 * t + 2], u3 = uv[4 * t + 3];
        u64 s01 = f2add(u0, u1), p01 = f2mul(u0, u1);
        u64 s23 = f2add(u2, u3), p23 = f2mul(u2, u3);
        u64 e1 = f2add(s01, s23);
        u64 e2 = f2fma(s01, s23, f2add(p01, p23));
        u64 e3 = f2fma(p01, s23, f2mul(p23, s01));
        u64 e4 = f2mul(p01, p23);
        u64 te1 = f2add(e1, f2add(e1, e1));   // 3*e1
        u64 te2 = f2add(e2, e2);              // 2*e2
        ulonglong2 A; A.x = e1; A.y = e2;
        ulonglong2 Bc; Bc.x = e3; Bc.y = e4;
        ulonglong2 C; C.x = te1; C.y = te2;
        tbl[3 * t] = A; tbl[3 * t + 1] = Bc; tbl[3 * t + 2] = C;
    }
    __syncthreads();

    const u64 ui2 = f2dup(ui);
    const u64 FOUR2 = f2dup(4.0f);
    u64 acc = 0ull;
#pragma unroll 8
    for (int g = 0; g < 32; g++) {
        ulonglong2 A = tbl[3 * g];         // e1, e2
        ulonglong2 Bc = tbl[3 * g + 1];    // e3, e4
        ulonglong2 C = tbl[3 * g + 2];     // 3e1, 2e2
        // P(ui) Horner
        u64 tP = f2add(ui2, A.x);
        tP = f2fma(tP, ui2, A.y);
        tP = f2fma(tP, ui2, Bc.x);
        tP = f2fma(tP, ui2, Bc.y);
        // P'(ui) Horner: 4x^3 + 3e1 x^2 + 2e2 x + e3
        u64 tD = f2fma(FOUR2, ui2, C.x);
        tD = f2fma(tD, ui2, C.y);
        tD = f2fma(tD, ui2, Bc.x);
        // rcp + accumulate P'/P
        float2 pu = f2unpack(tP);
        u64 rr = f2pack(frcp(pu.x), frcp(pu.y));
        acc = f2fma(tD, rr, acc);
    }
    float2 av = f2unpack(acc);
    float ssum = ui * (av.x + av.y);       // includes diagonal 0.5
    float neigh = exp2f(-(ssum - 0.5f) * LAM_INV_LOG2E);
    float contrib = neigh * d * g_factor[t];

#pragma unroll
    for (int o = 16; o; o >>= 1) contrib += __shfl_xor_sync(0xffffffffu, contrib, o);
    __syncthreads();               // red[] (dmax) reads all done
    if (lane == 0) red[warp] = contrib;
    __syncthreads();
    if (t == 0) {
        float s = red[0];
#pragma unroll
        for (int w = 1; w < 8; w++) s += red[w];
        g_part[b] = s;
    }

    // ---- last block: final loss assembly ----
    __shared__ unsigned int ticket;
    __threadfence();
    __syncthreads();
    if (t == 0) ticket = atomicAdd(&g_ctr, 1u);
    __syncthreads();
    if (ticket != (unsigned int)(gridDim.x - 1)) return;

    __shared__ float fin[24];
    float sd = 0.0f;
    const float4* gp4 = (const float4*)g_part;
#pragma unroll
    for (int p = 0; p < 4; p++) {
        float4 v = gp4[t + 256 * p];
        sd += (v.x + v.y) + (v.z + v.w);
    }
    float se = g_ep_rowsum[t];
    float sw = g_wl_rowsum[t];
#pragma unroll
    for (int o = 16; o; o >>= 1) {
        sd += __shfl_xor_sync(0xffffffffu, sd, o);
        se += __shfl_xor_sync(0xffffffffu, se, o);
        sw += __shfl_xor_sync(0xffffffffu, sw, o);
    }
    if (lane == 0) { fin[warp] = sd; fin[8 + warp] = se; fin[16 + warp] = sw; }
    __syncthreads();
    if (t == 0) {
        float data_sum = 0.0f, ep_sum = 0.0f, wl_sum = 0.0f;
#pragma unroll
        for (int w = 0; w < 8; w++) {
            data_sum += fin[w];
            ep_sum += fin[8 + w];
            wl_sum += fin[16 + w];
        }
        float data_term = data_sum * (1.0f / (float)(B_N * M_N));
        float weighted_len = wl_sum / (ep_sum + 1e-8f);
        float sparsity = ep_sum * (1.0f / (float)(M_N * M_N));
        out[0] = data_term + LEN_C * weighted_len + SP_C * sparsity;
    }
}

// ---------------- launch ----------------
extern "C" void kernel_launch(void* const* d_in, const int* in_sizes, int n_in,
                              void* d_out, int out_size) {
    const float* data = (const float*)d_in[0];     // [4096, 256]
    const float* weights = (const float*)d_in[1];  // [256, 256]
    const float* elog = (const float*)d_in[2];     // [256, 256]
    float* out = (float*)d_out;

    k_pre1<<<144, 256>>>(data, weights);
    k_edges<<<M_N / 4, 256>>>(weights, elog);
    k_gemm<<<B_N / GR, 128>>>(data);
    k_rank<<<B_N, 256>>>(out);
}

// round 10
// speedup vs baseline: 1.5808x; 1.2684x over previous
#include <cuda_runtime.h>
#include <cuda_bf16.h>
#include <math.h>

// Problem constants (fixed by setup_inputs)
#define B_N 4096
#define M_N 256
#define D_N 256

#define TAU_INV_LOG2E 7.213475204444817f   // log2(e)/0.2
#define LAM_INV_LOG2E 0.18033688011112043f // log2(e)/8
#define TOPO_C 0.5f
#define LEN_C 0.01f
#define SP_C 0.001f

typedef unsigned long long u64;

// ---------------- packed f32x2 helpers (sm_103a) ----------------
__device__ __forceinline__ u64 f2add(u64 a, u64 b) {
    u64 o; asm("add.rn.f32x2 %0, %1, %2;" : "=l"(o) : "l"(a), "l"(b)); return o;
}
__device__ __forceinline__ u64 f2mul(u64 a, u64 b) {
    u64 o; asm("mul.rn.f32x2 %0, %1, %2;" : "=l"(o) : "l"(a), "l"(b)); return o;
}
__device__ __forceinline__ u64 f2fma(u64 a, u64 b, u64 c) {
    u64 o; asm("fma.rn.f32x2 %0, %1, %2, %3;" : "=l"(o) : "l"(a), "l"(b), "l"(c)); return o;
}
__device__ __forceinline__ u64 f2dup(float x) {
    u64 o; asm("mov.b64 %0, {%1, %1};" : "=l"(o) : "f"(x)); return o;
}
__device__ __forceinline__ u64 f2pack(float x, float y) {
    u64 o; asm("mov.b64 %0, {%1, %2};" : "=l"(o) : "f"(x), "f"(y)); return o;
}
__device__ __forceinline__ float2 f2unpack(u64 v) {
    float2 o; asm("mov.b64 {%0, %1}, %2;" : "=f"(o.x), "=f"(o.y) : "l"(v)); return o;
}
__device__ __forceinline__ float frcp(float x) {
    float r; asm("rcp.approx.ftz.f32 %0, %1;" : "=f"(r) : "f"(x)); return r;
}

// ---------------- device scratch (no allocations allowed) ----------------
__device__ float g_Wtp[128 * 512];        // W transposed, k-pair-major: [k2][m][2], 256KB
__device__ float g_dist[B_N * M_N];       // 4 MB (stays L2-resident)
__device__ float g_wsq[M_N];
__device__ float g_factor[M_N];
__device__ float g_ep_rowsum[M_N];
__device__ float g_wl_rowsum[M_N];
__device__ float g_part[B_N];
__device__ unsigned int g_ctr;

// ---------------- K1: W prep only (wsq + transpose) + ctr reset ----------------
__global__ void __launch_bounds__(256) k_wprep(const float* __restrict__ W) {
    const int t = threadIdx.x;
    const int lane = t & 31, warp = t >> 5;
    __shared__ float Ws[16][260];

    if (blockIdx.x == 0 && t == 0) g_ctr = 0u;

    const int m0 = blockIdx.x * 16;
#pragma unroll
    for (int p = 0; p < 16; p++) {
        int q = t + p * 256;
        int r = q >> 8, k = q & 255;
        Ws[r][k] = W[(size_t)(m0 + r) * D_N + k];
    }
    __syncthreads();

#pragma unroll
    for (int rr = 0; rr < 2; rr++) {
        int row = warp * 2 + rr;
        float s = 0.0f;
#pragma unroll
        for (int p = 0; p < 8; p++) {
            float v = Ws[row][lane + 32 * p];
            s = fmaf(v, v, s);
        }
#pragma unroll
        for (int o = 16; o; o >>= 1) s += __shfl_xor_sync(0xffffffffu, s, o);
        if (lane == 0) g_wsq[m0 + row] = s;
    }

#pragma unroll
    for (int p = 0; p < 16; p++) {
        int k2 = p * 8 + warp;       // 0..127
        int mloc = lane >> 1, e = lane & 1;
        g_Wtp[k2 * 512 + (m0 + mloc) * 2 + e] = Ws[mloc][k2 * 2 + e];
    }
}

// ---------------- K2: mega = distance GEMM (blocks 0..255) + edges (blocks 256..319) ----------------
#define GR 16

__global__ void __launch_bounds__(128) k_mega(const float* __restrict__ X,
                                              const float* __restrict__ W,
                                              const float* __restrict__ E) {
    const int t = threadIdx.x;          // 0..127
    const int lane = t & 31, warp = t >> 5;

    __shared__ __align__(16) float Xs[GR][256];  // 16KB (edges branch aliases this)
    __shared__ __align__(16) float pool[8192];   // 32KB W chunk; later xsq scratch

    if (blockIdx.x < 256) {
        // ================= GEMM branch =================
        const int b0 = blockIdx.x * GR;
        const int m1 = t, m2 = t + 128;

        // load X tile: 1024 float4 / 128 threads
#pragma unroll
        for (int p = 0; p < 8; p++) {
            int q = t + p * 128;            // float4 idx 0..1023
            int r = q >> 6, c4 = q & 63;
            *(float4*)&Xs[r][c4 * 4] = ((const float4*)X)[(size_t)(b0 + r) * 64 + c4];
        }
        __syncthreads();

        u64 acc[GR][2];
#pragma unroll
        for (int r = 0; r < GR; r++) { acc[r][0] = 0ull; acc[r][1] = 0ull; }

        for (int chunk = 0; chunk < 8; chunk++) {
            const float4* src = (const float4*)(g_Wtp + chunk * 8192);
#pragma unroll
            for (int p = 0; p < 16; p++) {
                int idx = t + p * 128;
                ((float4*)pool)[idx] = src[idx];
            }
            __syncthreads();

#pragma unroll
            for (int k2 = 0; k2 < 16; k2 += 2) {
                u64 w0a = *(const u64*)&pool[k2 * 512 + m1 * 2];
                u64 w0b = *(const u64*)&pool[k2 * 512 + m2 * 2];
                u64 w1a = *(const u64*)&pool[(k2 + 1) * 512 + m1 * 2];
                u64 w1b = *(const u64*)&pool[(k2 + 1) * 512 + m2 * 2];
                int kg = (chunk * 16 + k2) * 2;     // 16B-aligned float idx
#pragma unroll
                for (int r = 0; r < GR; r++) {
                    ulonglong2 xv = *(const ulonglong2*)&Xs[r][kg];  // broadcast
                    acc[r][0] = f2fma(xv.x, w0a, acc[r][0]);
                    acc[r][1] = f2fma(xv.x, w0b, acc[r][1]);
                    acc[r][0] = f2fma(xv.y, w1a, acc[r][0]);
                    acc[r][1] = f2fma(xv.y, w1b, acc[r][1]);
                }
            }
            __syncthreads();
        }

        // xsq in-block: warp w reduces rows 4w..4w+3 from Xs; store into pool[0..15]
#pragma unroll
        for (int rr = 0; rr < 4; rr++) {
            int row = warp * 4 + rr;
            float s = 0.0f;
#pragma unroll
            for (int p = 0; p < 8; p++) {
                float v = Xs[row][lane + 32 * p];
                s = fmaf(v, v, s);
            }
#pragma unroll
            for (int o = 16; o; o >>= 1) s += __shfl_xor_sync(0xffffffffu, s, o);
            if (lane == 0) pool[row] = s;
        }
        __syncthreads();

        float wsq1 = g_wsq[m1], wsq2 = g_wsq[m2];
#pragma unroll
        for (int r = 0; r < GR; r++) {
            float xq = pool[r];
            float2 da = f2unpack(acc[r][0]);
            float2 db = f2unpack(acc[r][1]);
            float dot1 = da.x + da.y;
            float dot2 = db.x + db.y;
            g_dist[(size_t)(b0 + r) * M_N + m1] = sqrtf(fmaxf(xq + wsq1 - 2.0f * dot1, 0.0f));
            g_dist[(size_t)(b0 + r) * M_N + m2] = sqrtf(fmaxf(xq + wsq2 - 2.0f * dot2, 0.0f));
        }
        return;
    }

    // ================= EDGES branch (128 threads, 2 j-columns each) =================
    {
        const int i0 = (blockIdx.x - 256) * 4;
        float* wis = &Xs[0][0];              // 4 rows x 256 floats
        float* red_ep = &Xs[8][0];           // [4][4]
        float* red_wl = &Xs[8][16];          // [4][4]

#pragma unroll
        for (int p = 0; p < 8; p++) {
            int q = t + p * 128;
            int r = q >> 8, k = q & 255;
            wis[r * 256 + k] = W[(size_t)(i0 + r) * D_N + k];
        }
        __syncthreads();

        u64 acc[4][2];
#pragma unroll
        for (int i = 0; i < 4; i++) { acc[i][0] = 0ull; acc[i][1] = 0ull; }

        const float* wtp1 = g_Wtp + t * 2;
        const float* wtp2 = g_Wtp + (t + 128) * 2;
#pragma unroll 4
        for (int k2 = 0; k2 < 128; k2++) {
            u64 wj1 = *(const u64*)(wtp1 + k2 * 512);
            u64 wj2 = *(const u64*)(wtp2 + k2 * 512);
#pragma unroll
            for (int i = 0; i < 4; i++) {
                u64 xw = *(const u64*)&wis[i * 256 + 2 * k2];
                acc[i][0] = f2fma(xw, wj1, acc[i][0]);
                acc[i][1] = f2fma(xw, wj2, acc[i][1]);
            }
        }

        float wsq1 = g_wsq[t], wsq2 = g_wsq[t + 128];
#pragma unroll
        for (int i = 0; i < 4; i++) {
            int ig = i0 + i;
            float wsqi = g_wsq[ig];
            float sep, swl;
            {
                float2 q1 = f2unpack(acc[i][0]);
                float dot1 = q1.x + q1.y;
                float pd1 = fmaxf(wsqi + wsq1 - 2.0f * dot1, 0.0f);
                float l1 = 0.5f * (E[ig * M_N + t] + E[t * M_N + ig]);
                float ep1 = __fdividef(1.0f, 1.0f + __expf(-l1));
                if (t == ig) ep1 = 0.0f;

                float2 q2 = f2unpack(acc[i][1]);
                float dot2 = q2.x + q2.y;
                float pd2 = fmaxf(wsqi + wsq2 - 2.0f * dot2, 0.0f);
                float l2 = 0.5f * (E[ig * M_N + (t + 128)] + E[(t + 128) * M_N + ig]);
                float ep2 = __fdividef(1.0f, 1.0f + __expf(-l2));
                if (t + 128 == ig) ep2 = 0.0f;

                sep = ep1 + ep2;
                swl = ep1 * pd1 + ep2 * pd2;
            }
#pragma unroll
            for (int o = 16; o; o >>= 1) {
                sep += __shfl_xor_sync(0xffffffffu, sep, o);
                swl += __shfl_xor_sync(0xffffffffu, swl, o);
            }
            if (lane == 0) { red_ep[i * 4 + warp] = sep; red_wl[i * 4 + warp] = swl; }
        }
        __syncthreads();
        if (t < 4) {
            float rs = 0.0f, rw = 0.0f;
#pragma unroll
            for (int w = 0; w < 4; w++) { rs += red_ep[t * 4 + w]; rw += red_wl[t * 4 + w]; }
            int ig = i0 + t;
            g_ep_rowsum[ig] = rs;
            g_wl_rowsum[ig] = rw;
            g_factor[ig] = 1.0f + TOPO_C * (rs / (float)(M_N - 1));
        }
    }
}

// ---------------- K3: soft-rank via quartic + synthetic-division derivative ----------------
// P(x) = prod(x+u_k) over group of 4; Horner intermediates t1,t2,t3 give
// P'(x) = ((x+t1)x+t2)x+t3 for free -> tbl needs only {e1,e2},{e3,e4}.
// 8 fma + 2 LDS.128 + 2 RCP per 8 ordered pairs.
__global__ void __launch_bounds__(256) k_rank(float* __restrict__ out) {
    const int b = blockIdx.x;
    const int t = threadIdx.x;
    const int lane = t & 31, warp = t >> 5;

    __shared__ __align__(16) float us[256];        // interleaved u table (128 u64 pairs)
    __shared__ __align__(16) ulonglong2 tbl[64];   // 32 groups x {e1,e2},{e3,e4}
    __shared__ float red[8];

    float d = g_dist[(size_t)b * M_N + t];

    // row max
    float mx = d;
#pragma unroll
    for (int o = 16; o; o >>= 1) mx = fmaxf(mx, __shfl_xor_sync(0xffffffffu, mx, o));
    if (lane == 0) red[warp] = mx;
    __syncthreads();
    float dmax = red[0];
#pragma unroll
    for (int w = 1; w < 8; w++) dmax = fmaxf(dmax, red[w]);

    // u table (rescaled by 2^30; ratio-invariant). P in [2^-116, 2^124]: safe.
    float arg = fmaxf((d - dmax) * TAU_INV_LOG2E, -60.0f) + 30.0f;
    float ui = exp2f(arg);
    us[2 * (t & 127) + (t >> 7)] = ui;   // u64 slot k = (u_k, u_{k+128})
    __syncthreads();

    // build per-group coefficient tables (32 groups of 4 packed u's)
    if (t < 32) {
        const u64* uv = (const u64*)us;
        u64 u0 = uv[4 * t], u1 = uv[4 * t + 1], u2 = uv[4 * t + 2], u3 = uv[4 * t + 3];
        u64 s01 = f2add(u0, u1), p01 = f2mul(u0, u1);
        u64 s23 = f2add(u2, u3), p23 = f2mul(u2, u3);
        ulonglong2 A, Bc;
        A.x = f2add(s01, s23);                       // e1
        A.y = f2fma(s01, s23, f2add(p01, p23));      // e2
        Bc.x = f2fma(p01, s23, f2mul(p23, s01));     // e3
        Bc.y = f2mul(p01, p23);                      // e4
        tbl[2 * t] = A; tbl[2 * t + 1] = Bc;
    }
    __syncthreads();

    const u64 ui2 = f2dup(ui);
    u64 acc = 0ull;
#pragma unroll 8
    for (int g = 0; g < 32; g++) {
        ulonglong2 A = tbl[2 * g];         // e1, e2
        ulonglong2 Bc = tbl[2 * g + 1];    // e3, e4
        // P Horner with intermediates
        u64 t1 = f2add(ui2, A.x);
        u64 t2 = f2fma(t1, ui2, A.y);
        u64 t3 = f2fma(t2, ui2, Bc.x);
        u64 P  = f2fma(t3, ui2, Bc.y);
        // P' = ((x + t1)x + t2)x + t3  (synthetic division)
        u64 q1 = f2add(ui2, t1);
        u64 q2 = f2fma(q1, ui2, t2);
        u64 Dv = f2fma(q2, ui2, t3);
        // rcp + accumulate P'/P
        float2 pu = f2unpack(P);
        u64 rr = f2pack(frcp(pu.x), frcp(pu.y));
        acc = f2fma(Dv, rr, acc);
    }
    float2 av = f2unpack(acc);
    float ssum = ui * (av.x + av.y);       // includes diagonal 0.5
    float neigh = exp2f(-(ssum - 0.5f) * LAM_INV_LOG2E);
    float contrib = neigh * d * g_factor[t];

#pragma unroll
    for (int o = 16; o; o >>= 1) contrib += __shfl_xor_sync(0xffffffffu, contrib, o);
    __syncthreads();               // red[] (dmax) reads all done
    if (lane == 0) red[warp] = contrib;
    __syncthreads();
    if (t == 0) {
        float s = red[0];
#pragma unroll
        for (int w = 1; w < 8; w++) s += red[w];
        g_part[b] = s;
    }

    // ---- last block: final loss assembly ----
    __shared__ unsigned int ticket;
    __threadfence();
    __syncthreads();
    if (t == 0) ticket = atomicAdd(&g_ctr, 1u);
    __syncthreads();
    if (ticket != (unsigned int)(gridDim.x - 1)) return;

    __shared__ float fin[24];
    float sd = 0.0f;
    const float4* gp4 = (const float4*)g_part;
#pragma unroll
    for (int p = 0; p < 4; p++) {
        float4 v = gp4[t + 256 * p];
        sd += (v.x + v.y) + (v.z + v.w);
    }
    float se = g_ep_rowsum[t];
    float sw = g_wl_rowsum[t];
#pragma unroll
    for (int o = 16; o; o >>= 1) {
        sd += __shfl_xor_sync(0xffffffffu, sd, o);
        se += __shfl_xor_sync(0xffffffffu, se, o);
        sw += __shfl_xor_sync(0xffffffffu, sw, o);
    }
    if (lane == 0) { fin[warp] = sd; fin[8 + warp] = se; fin[16 + warp] = sw; }
    __syncthreads();
    if (t == 0) {
        float data_sum = 0.0f, ep_sum = 0.0f, wl_sum = 0.0f;
#pragma unroll
        for (int w = 0; w < 8; w++) {
            data_sum += fin[w];
            ep_sum += fin[8 + w];
            wl_sum += fin[16 + w];
        }
        float data_term = data_sum * (1.0f / (float)(B_N * M_N));
        float weighted_len = wl_sum / (ep_sum + 1e-8f);
        float sparsity = ep_sum * (1.0f / (float)(M_N * M_N));
        out[0] = data_term + LEN_C * weighted_len + SP_C * sparsity;
    }
}

// ---------------- launch ----------------
extern "C" void kernel_launch(void* const* d_in, const int* in_sizes, int n_in,
                              void* d_out, int out_size) {
    const float* data = (const float*)d_in[0];     // [4096, 256]
    const float* weights = (const float*)d_in[1];  // [256, 256]
    const float* elog = (const float*)d_in[2];     // [256, 256]
    float* out = (float*)d_out;

    k_wprep<<<16, 256>>>(weights);
    k_mega<<<320, 128>>>(data, weights, elog);
    k_rank<<<B_N, 256>>>(out);
}